// round 8
// baseline (speedup 1.0000x reference)
#include <cuda_runtime.h>
#include <cuda_bf16.h>
#include <math.h>

#define B_SZ 256
#define T_SZ 2048
#define H_SZ 128

// Scratch: layer-0 input projection pre0[b][t][j], 256 MiB. Order of CTAs for LPT.
__device__ float g_pre0[(size_t)B_SZ * T_SZ * H_SZ];
__device__ int g_order[B_SZ];

// ---------------------------------------------------------------------------
// Packed fp32x2 helpers (sm_103a FFMA2 path — bit-exact fp32, 2 FMA / instr)
// ---------------------------------------------------------------------------
__device__ __forceinline__ unsigned long long pack2(float lo, float hi) {
    unsigned long long r;
    asm("mov.b64 %0, {%1, %2};" : "=l"(r) : "f"(lo), "f"(hi));
    return r;
}
__device__ __forceinline__ float sum2(unsigned long long p) {
    float lo, hi;
    asm("mov.b64 {%0, %1}, %2;" : "=f"(lo), "=f"(hi) : "l"(p));
    return lo + hi;
}
__device__ __forceinline__ void ffma2(unsigned long long& acc,
                                      unsigned long long a, unsigned long long b) {
    asm("fma.rn.f32x2 %0, %1, %2, %0;" : "+l"(acc) : "l"(a), "l"(b));
}
__device__ __forceinline__ unsigned long long addf2(unsigned long long a,
                                                    unsigned long long b) {
    unsigned long long r;
    asm("add.rn.f32x2 %0, %1, %2;" : "=l"(r) : "l"(a), "l"(b));
    return r;
}

// Fast tanh: tanh(x) = 1 - 2/(exp2(x*2*log2e)+1). ex2/rcp.approx, abs err ~1e-7,
// branch-free, graceful saturation at +-1.
__device__ __forceinline__ float tanh_fast(float x) {
    float e;
    asm("ex2.approx.f32 %0, %1;" : "=f"(e) : "f"(x * 2.8853900817779268f));
    float r;
    asm("rcp.approx.f32 %0, %1;" : "=f"(r) : "f"(e + 1.0f));
    return fmaf(-2.0f, r, 1.0f);
}

// ---------------------------------------------------------------------------
// Kernel 0: sort batch indices by length descending (odd-even transposition).
// ---------------------------------------------------------------------------
__global__ void sort_kernel(const int* __restrict__ lengths) {
    __shared__ int key[B_SZ];
    __shared__ int idx[B_SZ];
    int tid = threadIdx.x;
    key[tid] = lengths[tid];
    idx[tid] = tid;
    __syncthreads();
    for (int p = 0; p < B_SZ; p++) {
        int i = 2 * tid + (p & 1);
        if (tid < 128 && i + 1 < B_SZ) {
            int ka = key[i], kb = key[i + 1];
            if (ka < kb) {  // descending
                key[i] = kb; key[i + 1] = ka;
                int t = idx[i]; idx[i] = idx[i + 1]; idx[i + 1] = t;
            }
        }
        __syncthreads();
    }
    g_order[tid] = idx[tid];
}

// ---------------------------------------------------------------------------
// Kernel 1: pre0[b][t][:] = emb[x[b][t]] @ W_ih[0] + b[0]   (only t < len[b],
// 64-token tiles). fp32x2-packed SIMT GEMM, W + token tile in smem.
// ---------------------------------------------------------------------------
#define PRE_SMEM (65536 + 32768 + 256)

__global__ __launch_bounds__(256, 2) void pre0_kernel(
    const int* __restrict__ x, const int* __restrict__ lengths,
    const float* __restrict__ emb, const float* __restrict__ W_ih,
    const float* __restrict__ bias)
{
    int b = blockIdx.y;
    int t0 = blockIdx.x * 64;
    if (t0 >= lengths[b]) return;

    extern __shared__ float smem[];
    float* Ws = smem;                    // [128][128]  W_ih layer 0
    float* Es = smem + 16384;            // [64][128]   embedding tile
    int*   toks = (int*)(smem + 24576);  // [64]

    int tid = threadIdx.x;

    const float4* W4 = (const float4*)W_ih;   // layer 0 at offset 0
    float4* Ws4 = (float4*)Ws;
#pragma unroll
    for (int i = 0; i < 16; i++) Ws4[tid + 256 * i] = W4[tid + 256 * i];
    if (tid < 64) toks[tid] = x[b * T_SZ + t0 + tid];
    __syncthreads();

    const float4* emb4 = (const float4*)emb;
    float4* Es4 = (float4*)Es;
#pragma unroll
    for (int i = 0; i < 8; i++) {
        int q = tid + 256 * i;
        int row = q >> 5, c = q & 31;
        Es4[q] = emb4[(size_t)toks[row] * 32 + c];
    }
    __syncthreads();

    int jj = tid & 31;     // column group: j = 4*jj .. 4*jj+3
    int tq = tid >> 5;     // token group: tokens tq*8 .. tq*8+7

    // accA[i] packs cols (4jj, 4jj+1); accB[i] packs cols (4jj+2, 4jj+3)
    unsigned long long accA[8], accB[8];
#pragma unroll
    for (int i = 0; i < 8; i++) { accA[i] = 0ull; accB[i] = 0ull; }

    const ulonglong2* Wrow2 = (const ulonglong2*)Ws;   // row-k, 16B per jj
#pragma unroll 4
    for (int k = 0; k < 128; k++) {
        ulonglong2 wv = Wrow2[k * 32 + jj];
#pragma unroll
        for (int i = 0; i < 8; i++) {
            float ev = Es[(tq * 8 + i) * 128 + k];  // warp broadcast
            unsigned long long evp = pack2(ev, ev);
            ffma2(accA[i], evp, wv.x);
            ffma2(accB[i], evp, wv.y);
        }
    }

    ulonglong2 bv = ((const ulonglong2*)bias)[jj];     // b[0][4jj..4jj+3]
    ulonglong2* out2 = (ulonglong2*)g_pre0;
#pragma unroll
    for (int i = 0; i < 8; i++) {
        int t = t0 + tq * 8 + i;
        ulonglong2 r;
        r.x = addf2(accA[i], bv.x);
        r.y = addf2(accB[i], bv.y);
        out2[((size_t)b * T_SZ + t) * 32 + jj] = r;
    }
}

// ---------------------------------------------------------------------------
// Kernel 2: persistent recurrent kernel, software-pipelined (3 barriers/step).
// One CTA per batch element (sorted longest-first). 512 threads; the 3
// recurrent weight matrices live in registers as packed fp32 pairs.
// Thread (kq, j): warp w = tid/32, kq = w>>2 covers k in [32*kq, 32*kq+32);
// j = (w&3)*32 + lane.
// Pipeline: pA holds W_hh0@h0(t) partials computed in the PREVIOUS step's P4.
//   P2: warps0-3 finalize h0'(t) from pA; all warps A2 = W_hh1@h1 -> reg acc2
//   P3: all warps A3 = W_ih1@h0'; write pB = acc2 + acc3
//   P4: warps4-7 finalize h1'(t) from pB; all warps A1(t+1)=W_hh0@h0' -> pA
// ---------------------------------------------------------------------------
__global__ __launch_bounds__(512, 1) void rnn_kernel(
    const int* __restrict__ lengths,
    const float* __restrict__ W_ih, const float* __restrict__ W_hh,
    const float* __restrict__ bias,
    const float* __restrict__ cls_w, const float* __restrict__ cls_b,
    float* __restrict__ out)
{
    __shared__ float h0[2][128];
    __shared__ float h1[2][128];
    __shared__ float pA[512];   // partials of W_hh0 @ h0   [kq][j]
    __shared__ float pB[512];   // partials of W_hh1@h1 + W_ih1@h0'  [kq][j]

    int tid = threadIdx.x;
    int lane = tid & 31;
    int w = tid >> 5;
    int kq = w >> 2;
    int j = (w & 3) * 32 + lane;
    int krow = kq * 32;

    int b = g_order[blockIdx.x];
    int len = lengths[b];

    const float* Whh0 = W_hh;                 // layer 0
    const float* Wih1 = W_ih + H_SZ * H_SZ;   // layer 1
    const float* Whh1 = W_hh + H_SZ * H_SZ;   // layer 1

    // Packed weight pairs over consecutive k: pair m = (krow+2m, krow+2m+1)
    unsigned long long wh0p[16], wi1p[16], wh1p[16];
#pragma unroll
    for (int m = 0; m < 16; m++) {
        int k0 = krow + 2 * m;
        wh0p[m] = pack2(Whh0[k0 * H_SZ + j], Whh0[(k0 + 1) * H_SZ + j]);
        wi1p[m] = pack2(Wih1[k0 * H_SZ + j], Wih1[(k0 + 1) * H_SZ + j]);
        wh1p[m] = pack2(Whh1[k0 * H_SZ + j], Whh1[(k0 + 1) * H_SZ + j]);
    }

    bool finA = (w < 4);             // finalizes h0 (owns pre_v)
    bool finB = (w >= 4 && w < 8);   // finalizes h1 (owns b1v)
    const float* preb = g_pre0 + (size_t)b * T_SZ * H_SZ;
    float pre_v = 0.f, b1v = 0.f;
    if (finA) pre_v = preb[j];       // t = 0
    if (finB) b1v = bias[H_SZ + j];  // b[1][j]

    // Prologue: h(0)=0 and pA=0 (== W_hh0 @ 0), so the steady-state loop is
    // correct from t=0.
    pA[tid] = 0.f;
    if (tid < 128) { h0[0][tid] = 0.f; h1[0][tid] = 0.f; }
    __syncthreads();

    for (int t = 0; t < len; t++) {
        int cur = t & 1, nxt = cur ^ 1;

        // ---- P2: finalize h0'(t) (warps 0-3) + A2 partials (all warps) ----
        if (finA) {
            float s = pre_v + pA[j] + pA[128 + j] + pA[256 + j] + pA[384 + j];
            pre_v = (t + 1 < len) ? __ldg(&preb[(size_t)(t + 1) * H_SZ + j]) : 0.f;
            h0[nxt][j] = tanh_fast(s);
        }
        unsigned long long acc2 = 0ull;
        {
            const ulonglong2* h1c = (const ulonglong2*)&h1[cur][krow];
#pragma unroll
            for (int i = 0; i < 8; i++) {
                ulonglong2 v = h1c[i];
                ffma2(acc2, wh1p[2 * i],     v.x);
                ffma2(acc2, wh1p[2 * i + 1], v.y);
            }
        }
        __syncthreads();   // h0[nxt] visible; pB safe to write (F1 read last step)

        // ---- P3: A3 partials on fresh h0'; single pB write ----
        unsigned long long acc1 = 0ull;
        {
            const ulonglong2* h0n = (const ulonglong2*)&h0[nxt][krow];
#pragma unroll
            for (int i = 0; i < 8; i++) {
                ulonglong2 v = h0n[i];
                ffma2(acc1, wi1p[2 * i],     v.x);
                ffma2(acc1, wi1p[2 * i + 1], v.y);
            }
        }
        pB[kq * 128 + j] = sum2(acc2) + sum2(acc1);
        __syncthreads();   // pB complete

        // ---- P4: finalize h1'(t) (warps 4-7) + A1(t+1) partials (all) ----
        if (finB) {
            float s = b1v + pB[j] + pB[128 + j] + pB[256 + j] + pB[384 + j];
            h1[nxt][j] = tanh_fast(s);
        }
        unsigned long long acc0 = 0ull;
        {
            const ulonglong2* h0n = (const ulonglong2*)&h0[nxt][krow];
#pragma unroll
            for (int i = 0; i < 8; i++) {
                ulonglong2 v = h0n[i];
                ffma2(acc0, wh0p[2 * i],     v.x);
                ffma2(acc0, wh0p[2 * i + 1], v.y);
            }
        }
        pA[kq * 128 + j] = sum2(acc0);
        __syncthreads();   // pA + h1[nxt] complete -> next iteration
    }

    // Classifier: sigmoid(h1_final @ cls_w + cls_b), warp 0
    if (w == 0) {
        int fb = len & 1;  // buffer written at t = len-1
        float s = 0.f;
#pragma unroll
        for (int q = 0; q < 4; q++)
            s += h1[fb][lane + 32 * q] * cls_w[lane + 32 * q];
#pragma unroll
        for (int o = 16; o > 0; o >>= 1)
            s += __shfl_down_sync(0xffffffffu, s, o);
        if (lane == 0)
            out[b] = 1.f / (1.f + expf(-(s + cls_b[0])));
    }
}

// ---------------------------------------------------------------------------
extern "C" void kernel_launch(void* const* d_in, const int* in_sizes, int n_in,
                              void* d_out, int out_size) {
    const int*   x       = (const int*)d_in[0];
    const int*   lengths = (const int*)d_in[1];
    const float* emb     = (const float*)d_in[2];
    const float* W_ih    = (const float*)d_in[3];
    const float* W_hh    = (const float*)d_in[4];
    const float* bias    = (const float*)d_in[5];
    const float* cls_w   = (const float*)d_in[6];
    const float* cls_b   = (const float*)d_in[7];
    float* out = (float*)d_out;

    sort_kernel<<<1, 256>>>(lengths);

    cudaFuncSetAttribute(pre0_kernel,
                         cudaFuncAttributeMaxDynamicSharedMemorySize, PRE_SMEM);
    dim3 grid(T_SZ / 64, B_SZ);
    pre0_kernel<<<grid, 256, PRE_SMEM>>>(x, lengths, emb, W_ih, bias);

    rnn_kernel<<<B_SZ, 512>>>(lengths, W_ih, W_hh, bias, cls_w, cls_b, out);
}

// round 14
// speedup vs baseline: 1.3562x; 1.3562x over previous
#include <cuda_runtime.h>
#include <cuda_bf16.h>
#include <math.h>

#define B_SZ 256
#define T_SZ 2048
#define H_SZ 128

// Scratch: layer-0 input projection pre0[b][t][j], 256 MiB. Order of CTAs for LPT.
__device__ float g_pre0[(size_t)B_SZ * T_SZ * H_SZ];
__device__ int g_order[B_SZ];

// ---------------------------------------------------------------------------
// Packed fp32x2 helpers (sm_103a FFMA2 path — bit-exact fp32, 2 FMA / instr)
// ---------------------------------------------------------------------------
__device__ __forceinline__ unsigned long long pack2(float lo, float hi) {
    unsigned long long r;
    asm("mov.b64 %0, {%1, %2};" : "=l"(r) : "f"(lo), "f"(hi));
    return r;
}
__device__ __forceinline__ float sum2(unsigned long long p) {
    float lo, hi;
    asm("mov.b64 {%0, %1}, %2;" : "=f"(lo), "=f"(hi) : "l"(p));
    return lo + hi;
}
__device__ __forceinline__ void ffma2(unsigned long long& acc,
                                      unsigned long long a, unsigned long long b) {
    asm("fma.rn.f32x2 %0, %1, %2, %0;" : "+l"(acc) : "l"(a), "l"(b));
}
__device__ __forceinline__ unsigned long long addf2(unsigned long long a,
                                                    unsigned long long b) {
    unsigned long long r;
    asm("add.rn.f32x2 %0, %1, %2;" : "=l"(r) : "l"(a), "l"(b));
    return r;
}

// Fast tanh: tanh(x) = 1 - 2/(exp2(x*2*log2e)+1). ex2/rcp.approx, abs err ~1e-7.
// Numerically validated in the R5 run (rel_err 4.7e-8).
__device__ __forceinline__ float tanh_fast(float x) {
    float e;
    asm("ex2.approx.f32 %0, %1;" : "=f"(e) : "f"(x * 2.8853900817779268f));
    float r;
    asm("rcp.approx.f32 %0, %1;" : "=f"(r) : "f"(e + 1.0f));
    return fmaf(-2.0f, r, 1.0f);
}

// ---------------------------------------------------------------------------
// Kernel 0: sort batch indices by length descending (odd-even transposition).
// ---------------------------------------------------------------------------
__global__ void sort_kernel(const int* __restrict__ lengths) {
    __shared__ int key[B_SZ];
    __shared__ int idx[B_SZ];
    int tid = threadIdx.x;
    key[tid] = lengths[tid];
    idx[tid] = tid;
    __syncthreads();
    for (int p = 0; p < B_SZ; p++) {
        int i = 2 * tid + (p & 1);
        if (tid < 128 && i + 1 < B_SZ) {
            int ka = key[i], kb = key[i + 1];
            if (ka < kb) {  // descending
                key[i] = kb; key[i + 1] = ka;
                int t = idx[i]; idx[i] = idx[i + 1]; idx[i + 1] = t;
            }
        }
        __syncthreads();
    }
    g_order[tid] = idx[tid];
}

// ---------------------------------------------------------------------------
// Kernel 1: pre0[b][t][:] = emb[x[b][t]] @ W_ih[0] + b[0]   (only t < len[b],
// 64-token tiles). fp32x2-packed SIMT GEMM, W + token tile in smem.
// ---------------------------------------------------------------------------
#define PRE_SMEM (65536 + 32768 + 256)

__global__ __launch_bounds__(256, 2) void pre0_kernel(
    const int* __restrict__ x, const int* __restrict__ lengths,
    const float* __restrict__ emb, const float* __restrict__ W_ih,
    const float* __restrict__ bias)
{
    int b = blockIdx.y;
    int t0 = blockIdx.x * 64;
    if (t0 >= lengths[b]) return;

    extern __shared__ float smem[];
    float* Ws = smem;                    // [128][128]  W_ih layer 0
    float* Es = smem + 16384;            // [64][128]   embedding tile
    int*   toks = (int*)(smem + 24576);  // [64]

    int tid = threadIdx.x;

    const float4* W4 = (const float4*)W_ih;   // layer 0 at offset 0
    float4* Ws4 = (float4*)Ws;
#pragma unroll
    for (int i = 0; i < 16; i++) Ws4[tid + 256 * i] = W4[tid + 256 * i];
    if (tid < 64) toks[tid] = x[b * T_SZ + t0 + tid];
    __syncthreads();

    const float4* emb4 = (const float4*)emb;
    float4* Es4 = (float4*)Es;
#pragma unroll
    for (int i = 0; i < 8; i++) {
        int q = tid + 256 * i;
        int row = q >> 5, c = q & 31;
        Es4[q] = emb4[(size_t)toks[row] * 32 + c];
    }
    __syncthreads();

    int jj = tid & 31;     // column group: j = 4*jj .. 4*jj+3
    int tq = tid >> 5;     // token group: tokens tq*8 .. tq*8+7

    // accA[i] packs cols (4jj, 4jj+1); accB[i] packs cols (4jj+2, 4jj+3)
    unsigned long long accA[8], accB[8];
#pragma unroll
    for (int i = 0; i < 8; i++) { accA[i] = 0ull; accB[i] = 0ull; }

    const ulonglong2* Wrow2 = (const ulonglong2*)Ws;   // row-k, 16B per jj
#pragma unroll 4
    for (int k = 0; k < 128; k++) {
        ulonglong2 wv = Wrow2[k * 32 + jj];
#pragma unroll
        for (int i = 0; i < 8; i++) {
            float ev = Es[(tq * 8 + i) * 128 + k];  // warp broadcast
            unsigned long long evp = pack2(ev, ev);
            ffma2(accA[i], evp, wv.x);
            ffma2(accB[i], evp, wv.y);
        }
    }

    ulonglong2 bv = ((const ulonglong2*)bias)[jj];     // b[0][4jj..4jj+3]
    ulonglong2* out2 = (ulonglong2*)g_pre0;
#pragma unroll
    for (int i = 0; i < 8; i++) {
        int t = t0 + tq * 8 + i;
        ulonglong2 r;
        r.x = addf2(accA[i], bv.x);
        r.y = addf2(accB[i], bv.y);
        out2[((size_t)b * T_SZ + t) * 32 + jj] = r;
    }
}

// ---------------------------------------------------------------------------
// Kernel 2: persistent recurrent kernel — measured-good 4-phase structure
// (R3, 1517.6us) + tanh_fast + LDS.128 h-state loads. NO register state
// lives across any __syncthreads() (R5's pipelined variant regressed to
// 2053us). Weight-pair mapping: ulonglong2 h[i] = packed pairs {2i, 2i+1}
// -> weights w*p[2i], w*p[2i+1]. (R8 scrambled this; fixed.)
// Thread (kq, j): warp w = tid/32, kq = w>>2 covers k in [32*kq, 32*kq+32);
// j = (w&3)*32 + lane.
// ---------------------------------------------------------------------------
__global__ __launch_bounds__(512, 1) void rnn_kernel(
    const int* __restrict__ lengths,
    const float* __restrict__ W_ih, const float* __restrict__ W_hh,
    const float* __restrict__ bias,
    const float* __restrict__ cls_w, const float* __restrict__ cls_b,
    float* __restrict__ out)
{
    __shared__ float h0[2][128];
    __shared__ float h1[2][128];
    __shared__ float pA[512];   // partials for h0 matvec  [kq][j]
    __shared__ float pB[512];   // partials for h1 matvecs [kq][j]

    int tid = threadIdx.x;
    int lane = tid & 31;
    int w = tid >> 5;
    int kq = w >> 2;
    int j = (w & 3) * 32 + lane;
    int krow = kq * 32;

    int b = g_order[blockIdx.x];
    int len = lengths[b];

    const float* Whh0 = W_hh;                 // layer 0
    const float* Wih1 = W_ih + H_SZ * H_SZ;   // layer 1
    const float* Whh1 = W_hh + H_SZ * H_SZ;   // layer 1

    // Packed weight pairs over consecutive k: pair m = (krow+2m, krow+2m+1)
    unsigned long long wh0p[16], wi1p[16], wh1p[16];
#pragma unroll
    for (int m = 0; m < 16; m++) {
        int k0 = krow + 2 * m;
        wh0p[m] = pack2(Whh0[k0 * H_SZ + j], Whh0[(k0 + 1) * H_SZ + j]);
        wi1p[m] = pack2(Wih1[k0 * H_SZ + j], Wih1[(k0 + 1) * H_SZ + j]);
        wh1p[m] = pack2(Whh1[k0 * H_SZ + j], Whh1[(k0 + 1) * H_SZ + j]);
    }

    bool finA = (w < 4);             // finalizes h0 (owns pre_v)
    bool finB = (w >= 4 && w < 8);   // finalizes h1 (owns b1v)
    const float* preb = g_pre0 + (size_t)b * T_SZ * H_SZ;
    float pre_v = 0.f, b1v = 0.f;
    if (finA) pre_v = preb[j];       // t = 0
    if (finB) b1v = bias[H_SZ + j];  // b[1][j]

    if (tid < 128) { h0[0][tid] = 0.f; h1[0][tid] = 0.f; }
    __syncthreads();

    for (int t = 0; t < len; t++) {
        int cur = t & 1, nxt = cur ^ 1;

        // Phase A: partials of h0@W_hh0 and h1@W_hh1 (two chains, LDS.128)
        unsigned long long acc0 = 0ull, acc2 = 0ull;
        {
            const ulonglong2* h0c = (const ulonglong2*)&h0[cur][krow];
            const ulonglong2* h1c = (const ulonglong2*)&h1[cur][krow];
#pragma unroll
            for (int i = 0; i < 8; i++) {
                ulonglong2 a = h0c[i];
                ulonglong2 c = h1c[i];
                ffma2(acc0, wh0p[2 * i],     a.x);
                ffma2(acc0, wh0p[2 * i + 1], a.y);
                ffma2(acc2, wh1p[2 * i],     c.x);
                ffma2(acc2, wh1p[2 * i + 1], c.y);
            }
        }
        pA[kq * 128 + j] = sum2(acc0);
        pB[kq * 128 + j] = sum2(acc2);
        __syncthreads();

        // Phase B: finalize h0' = tanh(pre0 + sum partials); prefetch next pre0
        if (finA) {
            float s = pre_v + pA[j] + pA[128 + j] + pA[256 + j] + pA[384 + j];
            pre_v = (t + 1 < len) ? __ldg(&preb[(size_t)(t + 1) * H_SZ + j]) : 0.f;
            h0[nxt][j] = tanh_fast(s);
        }
        __syncthreads();

        // Phase C: partials of h0'@W_ih1, accumulate into own pB slot
        unsigned long long acc1 = 0ull;
        {
            const ulonglong2* h0n = (const ulonglong2*)&h0[nxt][krow];
#pragma unroll
            for (int i = 0; i < 8; i++) {
                ulonglong2 v = h0n[i];
                ffma2(acc1, wi1p[2 * i],     v.x);
                ffma2(acc1, wi1p[2 * i + 1], v.y);
            }
        }
        pB[kq * 128 + j] += sum2(acc1);
        __syncthreads();

        // Phase D: finalize h1' = tanh(b1 + sum partials)
        if (finB) {
            float s = b1v + pB[j] + pB[128 + j] + pB[256 + j] + pB[384 + j];
            h1[nxt][j] = tanh_fast(s);
        }
        __syncthreads();
    }

    // Classifier: sigmoid(h1_final @ cls_w + cls_b), warp 0
    if (w == 0) {
        int fb = len & 1;  // buffer written at t = len-1
        float s = 0.f;
#pragma unroll
        for (int q = 0; q < 4; q++)
            s += h1[fb][lane + 32 * q] * cls_w[lane + 32 * q];
#pragma unroll
        for (int o = 16; o > 0; o >>= 1)
            s += __shfl_down_sync(0xffffffffu, s, o);
        if (lane == 0)
            out[b] = 1.f / (1.f + expf(-(s + cls_b[0])));
    }
}

// ---------------------------------------------------------------------------
extern "C" void kernel_launch(void* const* d_in, const int* in_sizes, int n_in,
                              void* d_out, int out_size) {
    const int*   x       = (const int*)d_in[0];
    const int*   lengths = (const int*)d_in[1];
    const float* emb     = (const float*)d_in[2];
    const float* W_ih    = (const float*)d_in[3];
    const float* W_hh    = (const float*)d_in[4];
    const float* bias    = (const float*)d_in[5];
    const float* cls_w   = (const float*)d_in[6];
    const float* cls_b   = (const float*)d_in[7];
    float* out = (float*)d_out;

    sort_kernel<<<1, 256>>>(lengths);

    cudaFuncSetAttribute(pre0_kernel,
                         cudaFuncAttributeMaxDynamicSharedMemorySize, PRE_SMEM);
    dim3 grid(T_SZ / 64, B_SZ);
    pre0_kernel<<<grid, 256, PRE_SMEM>>>(x, lengths, emb, W_ih, bias);

    rnn_kernel<<<B_SZ, 512>>>(lengths, W_ih, W_hh, bias, cls_w, cls_b, out);
}